// round 16
// baseline (speedup 1.0000x reference)
#include <cuda_runtime.h>
#include <cuda_bf16.h>
#include <cuda_fp16.h>
#include <math.h>
#include <stdint.h>

#define Bn 128
#define Tn 256
#define Sn 256
#define Hn 512
#define En 256
#define Vn 10000
#define H2 1024
#define H4 2048

typedef __half fp16;

#define GK 8   // gconst split-K factor

// ---------------- fp32 scratch ----------------
__device__ float g_h0[Bn * Hn];
__device__ float g_c0[Bn * Hn];
__device__ float g_qproj[Bn * Hn];
__device__ float g_part[Bn * Sn * 4];
__device__ float g_scores[Bn * Sn];
__device__ float g_gpart[GK * Bn * H4];
__device__ float g_gconst[Bn * H4];
__device__ float g_ctxP[Bn * Hn];

// ---------------- fp16 operands ----------------
__device__ fp16 g_embW[(size_t)Vn * H4];
__device__ fp16 g_embP[(size_t)Vn * Hn];
__device__ fp16 g_emb_h[(size_t)Vn * En];
__device__ fp16 g_Wih_h[(size_t)H4 * En];
__device__ fp16 g_pWe_h[(size_t)Hn * En];
__device__ fp16 g_key_h[(size_t)Hn * H2];
__device__ fp16 g_enc_h[(size_t)Bn * Sn * H2];
__device__ fp16 g_bhW_h[(size_t)Hn * H2];
__device__ fp16 g_bcW_h[(size_t)Hn * H2];
__device__ fp16 g_qW_h[(size_t)Hn * Hn];
__device__ fp16 g_eh_h[(size_t)Bn * H2];
__device__ fp16 g_ec_h[(size_t)Bn * H2];
__device__ fp16 g_h0h[(size_t)Bn * Hn];
__device__ fp16 g_xc_h[(size_t)Bn * 1536];    // [ctx | h0]
__device__ fp16 g_wc_h[(size_t)H4 * 1536];
__device__ fp16 g_pWh_h[(size_t)Hn * Hn];
__device__ fp16 g_pWc_h[(size_t)Hn * H2];
__device__ fp16 g_hh[(size_t)Bn * Tn * Hn];

__device__ __forceinline__ float sigf(float x) { return 1.f / (1.f + expf(-x)); }

// ================= PTX helpers =================
__device__ __forceinline__ uint32_t smem_u32(const void* p) {
    uint32_t a;
    asm("{ .reg .u64 t; cvta.to.shared.u64 t, %1; cvt.u32.u64 %0, t; }" : "=r"(a) : "l"(p));
    return a;
}
__device__ __forceinline__ void cp16(uint32_t dst, const void* src) {
    asm volatile("cp.async.cg.shared.global [%0], [%1], 16;" :: "r"(dst), "l"(src) : "memory");
}
__device__ __forceinline__ void ldsm4(uint32_t* r, uint32_t addr) {
    asm volatile("ldmatrix.sync.aligned.m8n8.x4.shared.b16 {%0,%1,%2,%3}, [%4];"
                 : "=r"(r[0]), "=r"(r[1]), "=r"(r[2]), "=r"(r[3]) : "r"(addr));
}
__device__ __forceinline__ void mma16h(float* c, const uint32_t* a, const uint32_t* b) {
    asm volatile("mma.sync.aligned.m16n8k16.row.col.f32.f16.f16.f32 "
                 "{%0,%1,%2,%3}, {%4,%5,%6,%7}, {%8,%9}, {%0,%1,%2,%3};"
                 : "+f"(c[0]), "+f"(c[1]), "+f"(c[2]), "+f"(c[3])
                 : "r"(a[0]), "r"(a[1]), "r"(a[2]), "r"(a[3]), "r"(b[0]), "r"(b[1]));
}

// ================= split fp16 GEMM-NT =================
#define NSTAGE 3
#define STAGE_BYTES 32768
#define SMEM_DYN (NSTAGE * STAGE_BYTES)

__device__ __forceinline__ void load_tiles(uint32_t base,
                                           const fp16* __restrict__ A, int lda,
                                           const fp16* __restrict__ W, int ldw,
                                           int m0, int n0, int k0, int M, bool guard, int tid)
{
    uint32_t ab = base, bb = base + 16384u;
    #pragma unroll
    for (int i = 0; i < 8; i++) {
        int c = tid + i * 128;
        int row = c >> 3, c16 = c & 7;
        uint32_t off = (uint32_t)(row * 128) + (uint32_t)((c16 ^ (row & 7)) << 4);
        int ar = m0 + row;
        if (guard && ar >= M) ar = M - 1;
        cp16(ab + off, A + (size_t)ar * lda + k0 + c16 * 8);
        cp16(bb + off, W + (size_t)(n0 + row) * ldw + k0 + c16 * 8);
    }
    asm volatile("cp.async.commit_group;" ::: "memory");
}

// EPI: 0 none (fp32 C); 1 C + embP16[tok] + ctxP; 2 tanh(acc+bias);
//      3 fused attention partials; 4 split-K partial; 5 fp16 output (Chi)
template<bool GUARD, int EPI>
__global__ __launch_bounds__(128, 2)
void mma_gemm(const fp16* __restrict__ Ah, const fp16* __restrict__ Al, int lda,
              const fp16* __restrict__ Wh, const fp16* __restrict__ Wl, int ldw,
              float* __restrict__ C, int ldc,
              int M, int K, int nkc,
              const float* __restrict__ bias,
              const int* __restrict__ tok,
              const float* __restrict__ embP,     // EPI=3: qproj (fp32); EPI=1: fp16 table
              const float* __restrict__ ctxP,
              fp16* __restrict__ Chi)
{
    extern __shared__ char dsm[];
    uint32_t sb = smem_u32(dsm);
    const int tid = threadIdx.x, wid = tid >> 5, lane = tid & 31;
    const int wm = wid & 1, wn = wid >> 1;        // warp tile 64x64
    const int m0 = blockIdx.y * 128, n0 = blockIdx.x * 128;
    const int kb = blockIdx.z * nkc;
    const int per = K >> 6;

    float acc[4][8][4];
    #pragma unroll
    for (int i = 0; i < 4; i++)
        #pragma unroll
        for (int j = 0; j < 8; j++)
            #pragma unroll
            for (int r = 0; r < 4; r++) acc[i][j][r] = 0.f;

    auto chunk = [&](int g, const fp16*& A, const fp16*& W, int& k0) {
        int p = g / per, r = g - p * per;
        k0 = r << 6;
        A = (p == 1) ? Al : Ah;
        W = (p == 2) ? Wl : Wh;
    };

    {
        const fp16 *A, *W; int k0;
        chunk(kb, A, W, k0);
        load_tiles(sb, A, lda, W, ldw, m0, n0, k0, M, GUARD, tid);
        chunk(kb + 1, A, W, k0);
        load_tiles(sb + STAGE_BYTES, A, lda, W, ldw, m0, n0, k0, M, GUARD, tid);
    }

    const int a_mi = lane >> 3, a_r = lane & 7;
    const int b_grp = lane >> 3, b_r = lane & 7;

    for (int j = 0; j < nkc; j++) {
        int nst = j + NSTAGE - 1;
        if (nst < nkc) {
            asm volatile("cp.async.wait_group %0;" :: "n"(NSTAGE - 2) : "memory");
            __syncthreads();
            const fp16 *A, *W; int k0;
            chunk(kb + nst, A, W, k0);
            load_tiles(sb + (uint32_t)(nst % NSTAGE) * STAGE_BYTES,
                       A, lda, W, ldw, m0, n0, k0, M, GUARD, tid);
        } else {
            asm volatile("cp.async.wait_group 0;" ::: "memory");   // tail drain
            __syncthreads();
        }

        uint32_t abase = sb + (uint32_t)(j % NSTAGE) * STAGE_BYTES;
        uint32_t bbase = abase + 16384u;
        #pragma unroll
        for (int k16 = 0; k16 < 4; k16++) {
            uint32_t af[4][4];
            #pragma unroll
            for (int mt = 0; mt < 4; mt++) {
                int row = wm * 64 + mt * 16 + ((a_mi & 1) << 3) + a_r;
                int c16 = (k16 << 1) + (a_mi >> 1);
                ldsm4(af[mt], abase + (uint32_t)(row * 128) + (uint32_t)((c16 ^ (row & 7)) << 4));
            }
            uint32_t bfl[16];
            #pragma unroll
            for (int p = 0; p < 4; p++) {
                int row = wn * 64 + p * 16 + ((b_grp >> 1) << 3) + b_r;
                int c16 = (k16 << 1) + (b_grp & 1);
                ldsm4(&bfl[p * 4], bbase + (uint32_t)(row * 128) + (uint32_t)((c16 ^ (row & 7)) << 4));
            }
            #pragma unroll
            for (int mt = 0; mt < 4; mt++)
                #pragma unroll
                for (int nt = 0; nt < 8; nt++)
                    mma16h(acc[mt][nt], af[mt], &bfl[nt * 2]);
        }
    }

    if (EPI == 3) {
        __syncthreads();
        float* sred = reinterpret_cast<float*>(dsm);
        #pragma unroll
        for (int mt = 0; mt < 4; mt++) {
            #pragma unroll
            for (int half = 0; half < 2; half++) {
                int rl = wm * 64 + mt * 16 + (lane >> 2) + half * 8;
                int row = m0 + rl;
                const float* q = embP + (size_t)(row >> 8) * Hn;   // qproj (fp32)
                float p = 0.f;
                #pragma unroll
                for (int nt = 0; nt < 8; nt++) {
                    int col = n0 + wn * 64 + nt * 8 + (lane & 3) * 2;
                    p += tanhf(acc[mt][nt][half * 2]     + q[col])     * bias[col];
                    p += tanhf(acc[mt][nt][half * 2 + 1] + q[col + 1]) * bias[col + 1];
                }
                p += __shfl_xor_sync(0xffffffffu, p, 1);
                p += __shfl_xor_sync(0xffffffffu, p, 2);
                if ((lane & 3) == 0) sred[rl * 2 + wn] = p;
            }
        }
        __syncthreads();
        if (tid < 128)
            C[(size_t)(m0 + tid) * 4 + blockIdx.x] = sred[tid * 2] + sred[tid * 2 + 1];
        return;
    }

    size_t zoff = (EPI == 4) ? (size_t)blockIdx.z * M : 0;
    #pragma unroll
    for (int mt = 0; mt < 4; mt++) {
        #pragma unroll
        for (int half = 0; half < 2; half++) {
            int row = m0 + wm * 64 + mt * 16 + (lane >> 2) + half * 8;
            if (GUARD && row >= M) continue;
            const fp16* ep16 = nullptr; const float* cq = nullptr;
            if (EPI == 1) {
                ep16 = reinterpret_cast<const fp16*>(embP) + (size_t)tok[row] * Hn;
                cq = ctxP + (size_t)(row >> 8) * Hn;
            }
            #pragma unroll
            for (int nt = 0; nt < 8; nt++) {
                int col = n0 + wn * 64 + nt * 8 + (lane & 3) * 2;
                float vx = acc[mt][nt][half * 2];
                float vy = acc[mt][nt][half * 2 + 1];
                if (EPI == 1) {
                    __half2 e2 = *reinterpret_cast<const __half2*>(ep16 + col);
                    vx += __half2float(e2.x) + cq[col];
                    vy += __half2float(e2.y) + cq[col + 1];
                }
                if (EPI == 2) {
                    vx = tanhf(vx + bias[col]);
                    vy = tanhf(vy + bias[col + 1]);
                }
                if (EPI == 5) {
                    *reinterpret_cast<__half2*>(Chi + (size_t)row * ldc + col) =
                        __halves2half2(__float2half(vx), __float2half(vy));
                } else {
                    *reinterpret_cast<float2*>(C + (zoff + row) * ldc + col) = make_float2(vx, vy);
                }
            }
        }
    }
}

// ================= fp32 -> fp16 conversions =================
__global__ void cvt1_flat(const float* __restrict__ src, fp16* __restrict__ dhi, int n4)
{
    const float4* s = reinterpret_cast<const float4*>(src);
    for (int i = blockIdx.x * blockDim.x + threadIdx.x; i < n4; i += gridDim.x * blockDim.x) {
        float4 v = s[i];
        fp16 hb[4] = {__float2half(v.x), __float2half(v.y), __float2half(v.z), __float2half(v.w)};
        *reinterpret_cast<uint2*>(dhi + (size_t)i * 4) = *reinterpret_cast<uint2*>(hb);
    }
}

__global__ void cvt1_kernel(const float* __restrict__ src, int lds,
                            fp16* __restrict__ dhi, int K)
{
    int row = blockIdx.x;
    const float* s = src + (size_t)row * lds;
    fp16* dh = dhi + (size_t)row * K;
    for (int k4 = threadIdx.x; k4 < K / 4; k4 += blockDim.x) {
        float4 v = *reinterpret_cast<const float4*>(s + k4 * 4);
        fp16 hb[4] = {__float2half(v.x), __float2half(v.y), __float2half(v.z), __float2half(v.w)};
        *reinterpret_cast<uint2*>(dh + k4 * 4) = *reinterpret_cast<uint2*>(hb);
    }
}

// wcat[n][1536] = fp16 of [W_ih[n, E:] | W_hh[n, :]]
__global__ void pack_wcat1(const float* __restrict__ W_ih, const float* __restrict__ W_hh) {
    int n = blockIdx.x;
    fp16* dh = g_wc_h + (size_t)n * 1536;
    const float* wi = W_ih + (size_t)n * (En + H2) + En;
    const float* wh = W_hh + (size_t)n * Hn;
    for (int k = threadIdx.x; k < 1536; k += blockDim.x)
        dh[k] = __float2half((k < H2) ? wi[k] : wh[k - H2]);
}
// xcat tail [1024:1536] = fp16 of h0
__global__ void xcat_h0() {
    int b = blockIdx.x;
    for (int k = threadIdx.x; k < Hn; k += blockDim.x)
        g_xc_h[(size_t)b * 1536 + H2 + k] = __float2half(g_h0[(size_t)b * Hn + k]);
}

// ================= attention small kernels =================
__global__ void softmaxP(const int* __restrict__ srcpos) {
    __shared__ float sm[8];
    int b = blockIdx.x, t = threadIdx.x, w = t >> 5, l = t & 31;
    int row = b * Sn + t;
    float4 pp = *reinterpret_cast<const float4*>(g_part + (size_t)row * 4);
    float v = (srcpos[row] != 0) ? (pp.x + pp.y + pp.z + pp.w) : -1e9f;
    float m = v;
    #pragma unroll
    for (int o = 16; o; o >>= 1) m = fmaxf(m, __shfl_xor_sync(0xffffffffu, m, o));
    if (l == 0) sm[w] = m;
    __syncthreads();
    m = sm[0];
    #pragma unroll
    for (int i = 1; i < 8; i++) m = fmaxf(m, sm[i]);
    __syncthreads();
    float e = expf(v - m);
    float s = e;
    #pragma unroll
    for (int o = 16; o; o >>= 1) s += __shfl_xor_sync(0xffffffffu, s, o);
    if (l == 0) sm[w] = s;
    __syncthreads();
    s = 0.f;
    #pragma unroll
    for (int i = 0; i < 8; i++) s += sm[i];
    g_scores[row] = e / s;
}

// context -> xcat[0:1024] fp16; reads fp16 enc_h (fp32 accumulate)
__global__ void context_kernel() {
    __shared__ float a[Sn];
    int b = blockIdx.x;
    int d = blockIdx.y * 256 + threadIdx.x;
    a[threadIdx.x] = g_scores[b * Sn + threadIdx.x];
    __syncthreads();
    const fp16* e = g_enc_h + (size_t)b * Sn * H2 + d;
    float s = 0.f;
    #pragma unroll 4
    for (int sS = 0; sS < Sn; sS++) s += a[sS] * __half2float(e[(size_t)sS * H2]);
    g_xc_h[(size_t)b * 1536 + d] = __float2half(s);
}

// gconst = deterministic sum of GK split-K partials
__global__ void reduceGK() {
    int i = blockIdx.x * 256 + threadIdx.x;
    const int N = Bn * H4;
    float s0 = (g_gpart[i] + g_gpart[i + N]) + (g_gpart[i + 2 * N] + g_gpart[i + 3 * N]);
    float s1 = (g_gpart[i + 4 * N] + g_gpart[i + 5 * N]) + (g_gpart[i + 6 * N] + g_gpart[i + 7 * N]);
    g_gconst[i] = s0 + s1;
}

// LSTM cell -> h (fp16); embW read as fp16
__global__ void gates_kernel(const int* __restrict__ tgt,
                             const float* __restrict__ b_ih,
                             const float* __restrict__ b_hh) {
    int row = blockIdx.x;
    int t = threadIdx.x;
    int b = row >> 8;
    int tok = tgt[row];
    const __half2* ew = reinterpret_cast<const __half2*>(g_embW + (size_t)tok * H4);
    const float2* gc = reinterpret_cast<const float2*>(g_gconst + (size_t)b * H4);
    const float2* bi = reinterpret_cast<const float2*>(b_ih);
    const float2* bh = reinterpret_cast<const float2*>(b_hh);
    const float2* c0 = reinterpret_cast<const float2*>(g_c0 + (size_t)b * Hn);
    float ex[4], ey[4];
    #pragma unroll
    for (int gidx = 0; gidx < 4; gidx++) {
        __half2 v = ew[t + gidx * 256];
        ex[gidx] = __half2float(v.x);
        ey[gidx] = __half2float(v.y);
    }
    float2 g0 = gc[t],       q0 = bi[t],       r0 = bh[t];
    float2 g1 = gc[t + 256], q1 = bi[t + 256], r1 = bh[t + 256];
    float2 g2 = gc[t + 512], q2 = bi[t + 512], r2 = bh[t + 512];
    float2 g3 = gc[t + 768], q3 = bi[t + 768], r3 = bh[t + 768];
    float2 cv = c0[t];
    float ix = ex[0] + g0.x + q0.x + r0.x, iy = ey[0] + g0.y + q0.y + r0.y;
    float fx = ex[1] + g1.x + q1.x + r1.x, fy = ey[1] + g1.y + q1.y + r1.y;
    float gx = ex[2] + g2.x + q2.x + r2.x, gy = ey[2] + g2.y + q2.y + r2.y;
    float ox = ex[3] + g3.x + q3.x + r3.x, oy = ey[3] + g3.y + q3.y + r3.y;
    float cx = sigf(fx) * cv.x + sigf(ix) * tanhf(gx);
    float cy = sigf(fy) * cv.y + sigf(iy) * tanhf(gy);
    float hx = sigf(ox) * tanhf(cx);
    float hy = sigf(oy) * tanhf(cy);
    reinterpret_cast<__half2*>(g_hh + (size_t)row * Hn)[t] =
        __halves2half2(__float2half(hx), __float2half(hy));
}

// ================= stream/event setup =================
static cudaStream_t g_s1, g_s2;
static cudaEvent_t g_eFork, g_eS2, g_eQ, g_eEmbW, g_eEmbP, g_eCtx, g_eCtxP, g_eE1;
namespace {
struct StreamInit {
    StreamInit() {
        cudaStreamCreateWithFlags(&g_s1, cudaStreamNonBlocking);
        cudaStreamCreateWithFlags(&g_s2, cudaStreamNonBlocking);
        cudaEventCreateWithFlags(&g_eFork, cudaEventDisableTiming);
        cudaEventCreateWithFlags(&g_eS2, cudaEventDisableTiming);
        cudaEventCreateWithFlags(&g_eQ, cudaEventDisableTiming);
        cudaEventCreateWithFlags(&g_eEmbW, cudaEventDisableTiming);
        cudaEventCreateWithFlags(&g_eEmbP, cudaEventDisableTiming);
        cudaEventCreateWithFlags(&g_eCtx, cudaEventDisableTiming);
        cudaEventCreateWithFlags(&g_eCtxP, cudaEventDisableTiming);
        cudaEventCreateWithFlags(&g_eE1, cudaEventDisableTiming);
    }
} g_streamInit;
}

static inline int cvt_grid(int n4) {
    int g = (n4 + 255) / 256;
    return g > 1184 ? 1184 : g;
}

// =========================================================================================
extern "C" void kernel_launch(void* const* d_in, const int* in_sizes, int n_in,
                              void* d_out, int out_size)
{
    const int*   tgt     = (const int*)  d_in[0];
    const float* enc     = (const float*)d_in[1];
    const float* eh      = (const float*)d_in[2];
    const float* ec      = (const float*)d_in[3];
    const int*   srcpos  = (const int*)  d_in[4];
    const float* emb     = (const float*)d_in[5];
    const float* key_W   = (const float*)d_in[6];
    const float* query_W = (const float*)d_in[7];
    const float* eW      = (const float*)d_in[8];
    const float* W_ih    = (const float*)d_in[9];
    const float* W_hh    = (const float*)d_in[10];
    const float* b_ih    = (const float*)d_in[11];
    const float* b_hh    = (const float*)d_in[12];
    const float* bhW     = (const float*)d_in[13];
    const float* bhb     = (const float*)d_in[14];
    const float* bcW     = (const float*)d_in[15];
    const float* bcb     = (const float*)d_in[16];
    const float* pre_W   = (const float*)d_in[17];
    float* out = (float*)d_out;

    float *p_h0, *p_c0, *p_qproj, *p_part, *p_ctxP, *p_gpart, *p_gconst;
    cudaGetSymbolAddress((void**)&p_h0, g_h0);
    cudaGetSymbolAddress((void**)&p_c0, g_c0);
    cudaGetSymbolAddress((void**)&p_qproj, g_qproj);
    cudaGetSymbolAddress((void**)&p_part, g_part);
    cudaGetSymbolAddress((void**)&p_ctxP, g_ctxP);
    cudaGetSymbolAddress((void**)&p_gpart, g_gpart);
    cudaGetSymbolAddress((void**)&p_gconst, g_gconst);

    fp16 *ew16, *ep16, *eb_h, *wi_h, *pe_h, *ky_h, *en_h;
    fp16 *bhh_, *bch_, *qwh, *ehh, *ech, *h0h, *xch, *wch, *pch, *phh, *hh;
    cudaGetSymbolAddress((void**)&ew16, g_embW);
    cudaGetSymbolAddress((void**)&ep16, g_embP);
    cudaGetSymbolAddress((void**)&eb_h, g_emb_h);
    cudaGetSymbolAddress((void**)&wi_h, g_Wih_h);
    cudaGetSymbolAddress((void**)&pe_h, g_pWe_h);
    cudaGetSymbolAddress((void**)&ky_h, g_key_h);
    cudaGetSymbolAddress((void**)&en_h, g_enc_h);
    cudaGetSymbolAddress((void**)&bhh_, g_bhW_h);
    cudaGetSymbolAddress((void**)&bch_, g_bcW_h);
    cudaGetSymbolAddress((void**)&qwh, g_qW_h);
    cudaGetSymbolAddress((void**)&ehh, g_eh_h);
    cudaGetSymbolAddress((void**)&ech, g_ec_h);
    cudaGetSymbolAddress((void**)&h0h, g_h0h);
    cudaGetSymbolAddress((void**)&xch, g_xc_h);
    cudaGetSymbolAddress((void**)&wch, g_wc_h);
    cudaGetSymbolAddress((void**)&pch, g_pWc_h);
    cudaGetSymbolAddress((void**)&phh, g_pWh_h);
    cudaGetSymbolAddress((void**)&hh, g_hh);

    cudaFuncSetAttribute(mma_gemm<false, 0>, cudaFuncAttributeMaxDynamicSharedMemorySize, SMEM_DYN);
    cudaFuncSetAttribute(mma_gemm<false, 1>, cudaFuncAttributeMaxDynamicSharedMemorySize, SMEM_DYN);
    cudaFuncSetAttribute(mma_gemm<false, 2>, cudaFuncAttributeMaxDynamicSharedMemorySize, SMEM_DYN);
    cudaFuncSetAttribute(mma_gemm<false, 3>, cudaFuncAttributeMaxDynamicSharedMemorySize, SMEM_DYN);
    cudaFuncSetAttribute(mma_gemm<false, 4>, cudaFuncAttributeMaxDynamicSharedMemorySize, SMEM_DYN);
    cudaFuncSetAttribute(mma_gemm<true, 5>,  cudaFuncAttributeMaxDynamicSharedMemorySize, SMEM_DYN);

    const int MH = (Bn * Sn) / 2;   // 16384 rows per PK chunk

    // ---- fork ----
    cudaEventRecord(g_eFork, 0);
    cudaStreamWaitEvent(g_s1, g_eFork, 0);
    cudaStreamWaitEvent(g_s2, g_eFork, 0);

    // ===== s1: enc cvt second half first (PK feed), then vocab precomputes =====
    cvt1_flat<<<1184, 256, 0, g_s1>>>(enc + (size_t)MH * H2, en_h + (size_t)MH * H2, MH * H2 / 4);
    cudaEventRecord(g_eE1, g_s1);
    cvt1_flat<<<cvt_grid(Vn * En / 4), 256, 0, g_s1>>>(emb, eb_h, Vn * En / 4);
    cvt1_kernel<<<H4, 64, 0, g_s1>>>(W_ih, En + H2, wi_h, En);
    cvt1_kernel<<<Hn, 64, 0, g_s1>>>(pre_W, En + Hn + H2, pe_h, En);
    mma_gemm<true, 5><<<dim3(H4 / 128, (Vn + 127) / 128), 128, SMEM_DYN, g_s1>>>(
        eb_h, eb_h, En, wi_h, wi_h, En, nullptr, H4, Vn, En, 4,
        nullptr, nullptr, nullptr, nullptr, ew16);
    cudaEventRecord(g_eEmbW, g_s1);
    mma_gemm<true, 5><<<dim3(Hn / 128, (Vn + 127) / 128), 128, SMEM_DYN, g_s1>>>(
        eb_h, eb_h, En, pe_h, pe_h, En, nullptr, Hn, Vn, En, 4,
        nullptr, nullptr, nullptr, nullptr, ep16);
    cudaEventRecord(g_eEmbP, g_s1);

    // ===== s2: qproj chain first (fp16 1-pass), then remaining weights =====
    cvt1_flat<<<cvt_grid(Hn * H2 / 4), 256, 0, g_s2>>>(bhW, bhh_, Hn * H2 / 4);
    cvt1_flat<<<cvt_grid(Bn * H2 / 4), 256, 0, g_s2>>>(eh, ehh, Bn * H2 / 4);
    cvt1_flat<<<cvt_grid(Hn * Hn / 4), 256, 0, g_s2>>>(query_W, qwh, Hn * Hn / 4);
    mma_gemm<false, 2><<<dim3(Hn / 128, 1), 128, SMEM_DYN, g_s2>>>(
        ehh, ehh, H2, bhh_, bhh_, H2, p_h0, Hn, Bn, H2, 16, bhb,
        nullptr, nullptr, nullptr, nullptr);
    cvt1_flat<<<cvt_grid(Bn * Hn / 4), 256, 0, g_s2>>>(p_h0, h0h, Bn * Hn / 4);
    mma_gemm<false, 0><<<dim3(Hn / 128, 1), 128, SMEM_DYN, g_s2>>>(
        h0h, h0h, Hn, qwh, qwh, Hn, p_qproj, Hn, Bn, Hn, 8,
        nullptr, nullptr, nullptr, nullptr, nullptr);
    cudaEventRecord(g_eQ, g_s2);
    xcat_h0<<<Bn, 256, 0, g_s2>>>();
    cvt1_flat<<<cvt_grid(Hn * H2 / 4), 256, 0, g_s2>>>(bcW, bch_, Hn * H2 / 4);
    cvt1_flat<<<cvt_grid(Bn * H2 / 4), 256, 0, g_s2>>>(ec, ech, Bn * H2 / 4);
    mma_gemm<false, 2><<<dim3(Hn / 128, 1), 128, SMEM_DYN, g_s2>>>(
        ech, ech, H2, bch_, bch_, H2, p_c0, Hn, Bn, H2, 16, bcb,
        nullptr, nullptr, nullptr, nullptr);
    pack_wcat1<<<H4, 256, 0, g_s2>>>(W_ih, W_hh);
    cvt1_kernel<<<Hn, 128, 0, g_s2>>>(pre_W + En, En + Hn + H2, phh, Hn);
    cvt1_kernel<<<Hn, 128, 0, g_s2>>>(pre_W + En + Hn, En + Hn + H2, pch, H2);
    cudaEventRecord(g_eS2, g_s2);

    // ===== s0: key + enc first-half cvt, PK in 2 row-chunks, attention =====
    cvt1_flat<<<cvt_grid(Hn * H2 / 4), 256>>>(key_W, ky_h, Hn * H2 / 4);
    cvt1_flat<<<1184, 256>>>(enc, en_h, MH * H2 / 4);
    cudaStreamWaitEvent(0, g_eQ, 0);
    mma_gemm<false, 3><<<dim3(Hn / 128, MH / 128), 128, SMEM_DYN>>>(
        en_h, en_h, H2, ky_h, ky_h, H2, p_part, 0, MH, H2, 16, eW,
        nullptr, p_qproj, nullptr, nullptr);
    cudaStreamWaitEvent(0, g_eE1, 0);
    mma_gemm<false, 3><<<dim3(Hn / 128, MH / 128), 128, SMEM_DYN>>>(
        en_h + (size_t)MH * H2, en_h + (size_t)MH * H2, H2, ky_h, ky_h, H2,
        p_part + (size_t)MH * 4, 0, MH, H2, 16, eW,
        nullptr, p_qproj + (size_t)(MH >> 8) * Hn, nullptr, nullptr);
    softmaxP<<<Bn, Sn>>>(srcpos);
    cudaStreamWaitEvent(0, g_eS2, 0);
    context_kernel<<<dim3(Bn, H2 / 256), 256>>>();
    cudaEventRecord(g_eCtx, 0);

    // ===== s2 continuation: ctxP concurrent with gconst =====
    cudaStreamWaitEvent(g_s2, g_eCtx, 0);
    mma_gemm<false, 0><<<dim3(Hn / 128, 1), 128, SMEM_DYN, g_s2>>>(
        xch, xch, 1536, pch, pch, H2, p_ctxP, Hn, Bn, H2, 16,
        nullptr, nullptr, nullptr, nullptr, nullptr);
    cudaEventRecord(g_eCtxP, g_s2);

    // ===== s0 continuation =====
    mma_gemm<false, 4><<<dim3(H4 / 128, 1, GK), 128, SMEM_DYN>>>(
        xch, xch, 1536, wch, wch, 1536, p_gpart, H4, Bn, 1536, 24 / GK,
        nullptr, nullptr, nullptr, nullptr, nullptr);
    reduceGK<<<(Bn * H4) / 256, 256>>>();
    cudaStreamWaitEvent(0, g_eEmbW, 0);
    gates_kernel<<<Bn * Tn, 256>>>(tgt, b_ih, b_hh);
    cudaStreamWaitEvent(0, g_eEmbP, 0);
    cudaStreamWaitEvent(0, g_eCtxP, 0);
    mma_gemm<false, 1><<<dim3(Hn / 128, (Bn * Tn) / 128), 128, SMEM_DYN>>>(
        hh, hh, Hn, phh, phh, Hn, out, Hn, Bn * Tn, Hn, 8,
        nullptr, tgt, (const float*)ep16, p_ctxP, nullptr);

    (void)in_sizes; (void)n_in; (void)out_size;
}

// round 17
// speedup vs baseline: 1.0143x; 1.0143x over previous
#include <cuda_runtime.h>
#include <cuda_bf16.h>
#include <cuda_fp16.h>
#include <math.h>
#include <stdint.h>

#define Bn 128
#define Tn 256
#define Sn 256
#define Hn 512
#define En 256
#define Vn 10000
#define H2 1024
#define H4 2048

typedef __half fp16;

#define GK 8   // gconst split-K factor

// ---------------- fp32 scratch ----------------
__device__ float g_h0[Bn * Hn];
__device__ float g_c0[Bn * Hn];
__device__ float g_qproj[Bn * Hn];
__device__ float g_part[Bn * Sn * 4];
__device__ float g_scores[Bn * Sn];
__device__ float g_gpart[GK * Bn * H4];
__device__ float g_gconst[Bn * H4];
__device__ float g_ctxP[Bn * Hn];

// ---------------- fp16 operands ----------------
__device__ fp16 g_embW[(size_t)Vn * H4];
__device__ fp16 g_embP[(size_t)Vn * Hn];
__device__ fp16 g_emb_h[(size_t)Vn * En];
__device__ fp16 g_Wih_h[(size_t)H4 * En];
__device__ fp16 g_pWe_h[(size_t)Hn * En];
__device__ fp16 g_key_h[(size_t)Hn * H2];
__device__ fp16 g_enc_h[(size_t)Bn * Sn * H2];
__device__ fp16 g_bhW_h[(size_t)Hn * H2];
__device__ fp16 g_bcW_h[(size_t)Hn * H2];
__device__ fp16 g_qW_h[(size_t)Hn * Hn];
__device__ fp16 g_eh_h[(size_t)Bn * H2];
__device__ fp16 g_ec_h[(size_t)Bn * H2];
__device__ fp16 g_h0h[(size_t)Bn * Hn];
__device__ fp16 g_xc_h[(size_t)Bn * 1536];    // [ctx | h0]
__device__ fp16 g_wc_h[(size_t)H4 * 1536];
__device__ fp16 g_pWh_h[(size_t)Hn * Hn];
__device__ fp16 g_pWc_h[(size_t)Hn * H2];
__device__ fp16 g_hh[(size_t)Bn * Tn * Hn];

__device__ __forceinline__ float sigf(float x) { return 1.f / (1.f + expf(-x)); }

// ================= PTX helpers =================
__device__ __forceinline__ uint32_t smem_u32(const void* p) {
    uint32_t a;
    asm("{ .reg .u64 t; cvta.to.shared.u64 t, %1; cvt.u32.u64 %0, t; }" : "=r"(a) : "l"(p));
    return a;
}
__device__ __forceinline__ void cp16(uint32_t dst, const void* src) {
    asm volatile("cp.async.cg.shared.global [%0], [%1], 16;" :: "r"(dst), "l"(src) : "memory");
}
__device__ __forceinline__ void ldsm4(uint32_t* r, uint32_t addr) {
    asm volatile("ldmatrix.sync.aligned.m8n8.x4.shared.b16 {%0,%1,%2,%3}, [%4];"
                 : "=r"(r[0]), "=r"(r[1]), "=r"(r[2]), "=r"(r[3]) : "r"(addr));
}
__device__ __forceinline__ void mma16h(float* c, const uint32_t* a, const uint32_t* b) {
    asm volatile("mma.sync.aligned.m16n8k16.row.col.f32.f16.f16.f32 "
                 "{%0,%1,%2,%3}, {%4,%5,%6,%7}, {%8,%9}, {%0,%1,%2,%3};"
                 : "+f"(c[0]), "+f"(c[1]), "+f"(c[2]), "+f"(c[3])
                 : "r"(a[0]), "r"(a[1]), "r"(a[2]), "r"(a[3]), "r"(b[0]), "r"(b[1]));
}

// ================= split fp16 GEMM-NT =================
#define NSTAGE 3
#define STAGE_BYTES 32768
#define SMEM_DYN (NSTAGE * STAGE_BYTES)

__device__ __forceinline__ void load_tiles(uint32_t base,
                                           const fp16* __restrict__ A, int lda,
                                           const fp16* __restrict__ W, int ldw,
                                           int m0, int n0, int k0, int M, bool guard, int tid)
{
    uint32_t ab = base, bb = base + 16384u;
    #pragma unroll
    for (int i = 0; i < 8; i++) {
        int c = tid + i * 128;
        int row = c >> 3, c16 = c & 7;
        uint32_t off = (uint32_t)(row * 128) + (uint32_t)((c16 ^ (row & 7)) << 4);
        int ar = m0 + row;
        if (guard && ar >= M) ar = M - 1;
        cp16(ab + off, A + (size_t)ar * lda + k0 + c16 * 8);
        cp16(bb + off, W + (size_t)(n0 + row) * ldw + k0 + c16 * 8);
    }
    asm volatile("cp.async.commit_group;" ::: "memory");
}

// EPI: 0 none (fp32 C); 1 C + embP16[tok] + ctxP; 2 tanh(acc+bias);
//      3 fused attention partials; 4 split-K partial; 5 fp16 output (Chi)
template<bool GUARD, int EPI>
__global__ __launch_bounds__(128, 2)
void mma_gemm(const fp16* __restrict__ Ah, const fp16* __restrict__ Al, int lda,
              const fp16* __restrict__ Wh, const fp16* __restrict__ Wl, int ldw,
              float* __restrict__ C, int ldc,
              int M, int K, int nkc,
              const float* __restrict__ bias,
              const int* __restrict__ tok,
              const float* __restrict__ embP,     // EPI=3: qproj (fp32); EPI=1: fp16 table
              const float* __restrict__ ctxP,
              fp16* __restrict__ Chi)
{
    extern __shared__ char dsm[];
    uint32_t sb = smem_u32(dsm);
    const int tid = threadIdx.x, wid = tid >> 5, lane = tid & 31;
    const int wm = wid & 1, wn = wid >> 1;        // warp tile 64x64
    const int m0 = blockIdx.y * 128, n0 = blockIdx.x * 128;
    const int kb = blockIdx.z * nkc;
    const int per = K >> 6;

    float acc[4][8][4];
    #pragma unroll
    for (int i = 0; i < 4; i++)
        #pragma unroll
        for (int j = 0; j < 8; j++)
            #pragma unroll
            for (int r = 0; r < 4; r++) acc[i][j][r] = 0.f;

    auto chunk = [&](int g, const fp16*& A, const fp16*& W, int& k0) {
        int p = g / per, r = g - p * per;
        k0 = r << 6;
        A = (p == 1) ? Al : Ah;
        W = (p == 2) ? Wl : Wh;
    };

    {
        const fp16 *A, *W; int k0;
        chunk(kb, A, W, k0);
        load_tiles(sb, A, lda, W, ldw, m0, n0, k0, M, GUARD, tid);
        chunk(kb + 1, A, W, k0);
        load_tiles(sb + STAGE_BYTES, A, lda, W, ldw, m0, n0, k0, M, GUARD, tid);
    }

    const int a_mi = lane >> 3, a_r = lane & 7;
    const int b_grp = lane >> 3, b_r = lane & 7;

    for (int j = 0; j < nkc; j++) {
        int nst = j + NSTAGE - 1;
        if (nst < nkc) {
            asm volatile("cp.async.wait_group %0;" :: "n"(NSTAGE - 2) : "memory");
            __syncthreads();
            const fp16 *A, *W; int k0;
            chunk(kb + nst, A, W, k0);
            load_tiles(sb + (uint32_t)(nst % NSTAGE) * STAGE_BYTES,
                       A, lda, W, ldw, m0, n0, k0, M, GUARD, tid);
        } else {
            asm volatile("cp.async.wait_group 0;" ::: "memory");   // tail drain
            __syncthreads();
        }

        uint32_t abase = sb + (uint32_t)(j % NSTAGE) * STAGE_BYTES;
        uint32_t bbase = abase + 16384u;
        #pragma unroll
        for (int k16 = 0; k16 < 4; k16++) {
            uint32_t af[4][4];
            #pragma unroll
            for (int mt = 0; mt < 4; mt++) {
                int row = wm * 64 + mt * 16 + ((a_mi & 1) << 3) + a_r;
                int c16 = (k16 << 1) + (a_mi >> 1);
                ldsm4(af[mt], abase + (uint32_t)(row * 128) + (uint32_t)((c16 ^ (row & 7)) << 4));
            }
            uint32_t bfl[16];
            #pragma unroll
            for (int p = 0; p < 4; p++) {
                int row = wn * 64 + p * 16 + ((b_grp >> 1) << 3) + b_r;
                int c16 = (k16 << 1) + (b_grp & 1);
                ldsm4(&bfl[p * 4], bbase + (uint32_t)(row * 128) + (uint32_t)((c16 ^ (row & 7)) << 4));
            }
            #pragma unroll
            for (int mt = 0; mt < 4; mt++)
                #pragma unroll
                for (int nt = 0; nt < 8; nt++)
                    mma16h(acc[mt][nt], af[mt], &bfl[nt * 2]);
        }
    }

    if (EPI == 3) {
        __syncthreads();
        float* sred = reinterpret_cast<float*>(dsm);
        #pragma unroll
        for (int mt = 0; mt < 4; mt++) {
            #pragma unroll
            for (int half = 0; half < 2; half++) {
                int rl = wm * 64 + mt * 16 + (lane >> 2) + half * 8;
                int row = m0 + rl;
                const float* q = embP + (size_t)(row >> 8) * Hn;   // qproj (fp32)
                float p = 0.f;
                #pragma unroll
                for (int nt = 0; nt < 8; nt++) {
                    int col = n0 + wn * 64 + nt * 8 + (lane & 3) * 2;
                    p += tanhf(acc[mt][nt][half * 2]     + q[col])     * bias[col];
                    p += tanhf(acc[mt][nt][half * 2 + 1] + q[col + 1]) * bias[col + 1];
                }
                p += __shfl_xor_sync(0xffffffffu, p, 1);
                p += __shfl_xor_sync(0xffffffffu, p, 2);
                if ((lane & 3) == 0) sred[rl * 2 + wn] = p;
            }
        }
        __syncthreads();
        if (tid < 128)
            C[(size_t)(m0 + tid) * 4 + blockIdx.x] = sred[tid * 2] + sred[tid * 2 + 1];
        return;
    }

    size_t zoff = (EPI == 4) ? (size_t)blockIdx.z * M : 0;
    #pragma unroll
    for (int mt = 0; mt < 4; mt++) {
        #pragma unroll
        for (int half = 0; half < 2; half++) {
            int row = m0 + wm * 64 + mt * 16 + (lane >> 2) + half * 8;
            if (GUARD && row >= M) continue;
            const fp16* ep16 = nullptr; const float* cq = nullptr;
            if (EPI == 1) {
                ep16 = reinterpret_cast<const fp16*>(embP) + (size_t)tok[row] * Hn;
                cq = ctxP + (size_t)(row >> 8) * Hn;
            }
            #pragma unroll
            for (int nt = 0; nt < 8; nt++) {
                int col = n0 + wn * 64 + nt * 8 + (lane & 3) * 2;
                float vx = acc[mt][nt][half * 2];
                float vy = acc[mt][nt][half * 2 + 1];
                if (EPI == 1) {
                    __half2 e2 = *reinterpret_cast<const __half2*>(ep16 + col);
                    vx += __half2float(e2.x) + cq[col];
                    vy += __half2float(e2.y) + cq[col + 1];
                }
                if (EPI == 2) {
                    vx = tanhf(vx + bias[col]);
                    vy = tanhf(vy + bias[col + 1]);
                }
                if (EPI == 5) {
                    *reinterpret_cast<__half2*>(Chi + (size_t)row * ldc + col) =
                        __halves2half2(__float2half(vx), __float2half(vy));
                } else {
                    *reinterpret_cast<float2*>(C + (zoff + row) * ldc + col) = make_float2(vx, vy);
                }
            }
        }
    }
}

// ================= fp32 -> fp16 conversions =================
__global__ void cvt1_flat(const float* __restrict__ src, fp16* __restrict__ dhi, int n4)
{
    const float4* s = reinterpret_cast<const float4*>(src);
    for (int i = blockIdx.x * blockDim.x + threadIdx.x; i < n4; i += gridDim.x * blockDim.x) {
        float4 v = s[i];
        fp16 hb[4] = {__float2half(v.x), __float2half(v.y), __float2half(v.z), __float2half(v.w)};
        *reinterpret_cast<uint2*>(dhi + (size_t)i * 4) = *reinterpret_cast<uint2*>(hb);
    }
}

__global__ void cvt1_kernel(const float* __restrict__ src, int lds,
                            fp16* __restrict__ dhi, int K)
{
    int row = blockIdx.x;
    const float* s = src + (size_t)row * lds;
    fp16* dh = dhi + (size_t)row * K;
    for (int k4 = threadIdx.x; k4 < K / 4; k4 += blockDim.x) {
        float4 v = *reinterpret_cast<const float4*>(s + k4 * 4);
        fp16 hb[4] = {__float2half(v.x), __float2half(v.y), __float2half(v.z), __float2half(v.w)};
        *reinterpret_cast<uint2*>(dh + k4 * 4) = *reinterpret_cast<uint2*>(hb);
    }
}

// wcat[n][1536] = fp16 of [W_ih[n, E:] | W_hh[n, :]]
__global__ void pack_wcat1(const float* __restrict__ W_ih, const float* __restrict__ W_hh) {
    int n = blockIdx.x;
    fp16* dh = g_wc_h + (size_t)n * 1536;
    const float* wi = W_ih + (size_t)n * (En + H2) + En;
    const float* wh = W_hh + (size_t)n * Hn;
    for (int k = threadIdx.x; k < 1536; k += blockDim.x)
        dh[k] = __float2half((k < H2) ? wi[k] : wh[k - H2]);
}
// xcat tail [1024:1536] = fp16 of h0
__global__ void xcat_h0() {
    int b = blockIdx.x;
    for (int k = threadIdx.x; k < Hn; k += blockDim.x)
        g_xc_h[(size_t)b * 1536 + H2 + k] = __float2half(g_h0[(size_t)b * Hn + k]);
}

// ================= attention small kernels =================
__global__ void softmaxP(const int* __restrict__ srcpos) {
    __shared__ float sm[8];
    int b = blockIdx.x, t = threadIdx.x, w = t >> 5, l = t & 31;
    int row = b * Sn + t;
    float4 pp = *reinterpret_cast<const float4*>(g_part + (size_t)row * 4);
    float v = (srcpos[row] != 0) ? (pp.x + pp.y + pp.z + pp.w) : -1e9f;
    float m = v;
    #pragma unroll
    for (int o = 16; o; o >>= 1) m = fmaxf(m, __shfl_xor_sync(0xffffffffu, m, o));
    if (l == 0) sm[w] = m;
    __syncthreads();
    m = sm[0];
    #pragma unroll
    for (int i = 1; i < 8; i++) m = fmaxf(m, sm[i]);
    __syncthreads();
    float e = expf(v - m);
    float s = e;
    #pragma unroll
    for (int o = 16; o; o >>= 1) s += __shfl_xor_sync(0xffffffffu, s, o);
    if (l == 0) sm[w] = s;
    __syncthreads();
    s = 0.f;
    #pragma unroll
    for (int i = 0; i < 8; i++) s += sm[i];
    g_scores[row] = e / s;
}

// context -> xcat[0:1024] fp16; reads fp16 enc_h (fp32 accumulate)
__global__ void context_kernel() {
    __shared__ float a[Sn];
    int b = blockIdx.x;
    int d = blockIdx.y * 256 + threadIdx.x;
    a[threadIdx.x] = g_scores[b * Sn + threadIdx.x];
    __syncthreads();
    const fp16* e = g_enc_h + (size_t)b * Sn * H2 + d;
    float s = 0.f;
    #pragma unroll 4
    for (int sS = 0; sS < Sn; sS++) s += a[sS] * __half2float(e[(size_t)sS * H2]);
    g_xc_h[(size_t)b * 1536 + d] = __float2half(s);
}

// gconst = deterministic sum of GK split-K partials
__global__ void reduceGK() {
    int i = blockIdx.x * 256 + threadIdx.x;
    const int N = Bn * H4;
    float s0 = (g_gpart[i] + g_gpart[i + N]) + (g_gpart[i + 2 * N] + g_gpart[i + 3 * N]);
    float s1 = (g_gpart[i + 4 * N] + g_gpart[i + 5 * N]) + (g_gpart[i + 6 * N] + g_gpart[i + 7 * N]);
    g_gconst[i] = s0 + s1;
}

// LSTM cell -> h (fp16); embW read as fp16
__global__ void gates_kernel(const int* __restrict__ tgt,
                             const float* __restrict__ b_ih,
                             const float* __restrict__ b_hh) {
    int row = blockIdx.x;
    int t = threadIdx.x;
    int b = row >> 8;
    int tok = tgt[row];
    const __half2* ew = reinterpret_cast<const __half2*>(g_embW + (size_t)tok * H4);
    const float2* gc = reinterpret_cast<const float2*>(g_gconst + (size_t)b * H4);
    const float2* bi = reinterpret_cast<const float2*>(b_ih);
    const float2* bh = reinterpret_cast<const float2*>(b_hh);
    const float2* c0 = reinterpret_cast<const float2*>(g_c0 + (size_t)b * Hn);
    float ex[4], ey[4];
    #pragma unroll
    for (int gidx = 0; gidx < 4; gidx++) {
        __half2 v = ew[t + gidx * 256];
        ex[gidx] = __half2float(v.x);
        ey[gidx] = __half2float(v.y);
    }
    float2 g0 = gc[t],       q0 = bi[t],       r0 = bh[t];
    float2 g1 = gc[t + 256], q1 = bi[t + 256], r1 = bh[t + 256];
    float2 g2 = gc[t + 512], q2 = bi[t + 512], r2 = bh[t + 512];
    float2 g3 = gc[t + 768], q3 = bi[t + 768], r3 = bh[t + 768];
    float2 cv = c0[t];
    float ix = ex[0] + g0.x + q0.x + r0.x, iy = ey[0] + g0.y + q0.y + r0.y;
    float fx = ex[1] + g1.x + q1.x + r1.x, fy = ey[1] + g1.y + q1.y + r1.y;
    float gx = ex[2] + g2.x + q2.x + r2.x, gy = ey[2] + g2.y + q2.y + r2.y;
    float ox = ex[3] + g3.x + q3.x + r3.x, oy = ey[3] + g3.y + q3.y + r3.y;
    float cx = sigf(fx) * cv.x + sigf(ix) * tanhf(gx);
    float cy = sigf(fy) * cv.y + sigf(iy) * tanhf(gy);
    float hx = sigf(ox) * tanhf(cx);
    float hy = sigf(oy) * tanhf(cy);
    reinterpret_cast<__half2*>(g_hh + (size_t)row * Hn)[t] =
        __halves2half2(__float2half(hx), __float2half(hy));
}

// ================= stream/event setup =================
static cudaStream_t g_s1, g_s2;
static cudaEvent_t g_eFork, g_eS2, g_eQ, g_eEmbW, g_eEmbP, g_eCtx, g_eCtxP;
namespace {
struct StreamInit {
    StreamInit() {
        cudaStreamCreateWithFlags(&g_s1, cudaStreamNonBlocking);
        cudaStreamCreateWithFlags(&g_s2, cudaStreamNonBlocking);
        cudaEventCreateWithFlags(&g_eFork, cudaEventDisableTiming);
        cudaEventCreateWithFlags(&g_eS2, cudaEventDisableTiming);
        cudaEventCreateWithFlags(&g_eQ, cudaEventDisableTiming);
        cudaEventCreateWithFlags(&g_eEmbW, cudaEventDisableTiming);
        cudaEventCreateWithFlags(&g_eEmbP, cudaEventDisableTiming);
        cudaEventCreateWithFlags(&g_eCtx, cudaEventDisableTiming);
        cudaEventCreateWithFlags(&g_eCtxP, cudaEventDisableTiming);
    }
} g_streamInit;
}

static inline int cvt_grid(int n4) {
    int g = (n4 + 255) / 256;
    return g > 1184 ? 1184 : g;
}

// =========================================================================================
extern "C" void kernel_launch(void* const* d_in, const int* in_sizes, int n_in,
                              void* d_out, int out_size)
{
    const int*   tgt     = (const int*)  d_in[0];
    const float* enc     = (const float*)d_in[1];
    const float* eh      = (const float*)d_in[2];
    const float* ec      = (const float*)d_in[3];
    const int*   srcpos  = (const int*)  d_in[4];
    const float* emb     = (const float*)d_in[5];
    const float* key_W   = (const float*)d_in[6];
    const float* query_W = (const float*)d_in[7];
    const float* eW      = (const float*)d_in[8];
    const float* W_ih    = (const float*)d_in[9];
    const float* W_hh    = (const float*)d_in[10];
    const float* b_ih    = (const float*)d_in[11];
    const float* b_hh    = (const float*)d_in[12];
    const float* bhW     = (const float*)d_in[13];
    const float* bhb     = (const float*)d_in[14];
    const float* bcW     = (const float*)d_in[15];
    const float* bcb     = (const float*)d_in[16];
    const float* pre_W   = (const float*)d_in[17];
    float* out = (float*)d_out;

    float *p_h0, *p_c0, *p_qproj, *p_part, *p_ctxP, *p_gpart, *p_gconst;
    cudaGetSymbolAddress((void**)&p_h0, g_h0);
    cudaGetSymbolAddress((void**)&p_c0, g_c0);
    cudaGetSymbolAddress((void**)&p_qproj, g_qproj);
    cudaGetSymbolAddress((void**)&p_part, g_part);
    cudaGetSymbolAddress((void**)&p_ctxP, g_ctxP);
    cudaGetSymbolAddress((void**)&p_gpart, g_gpart);
    cudaGetSymbolAddress((void**)&p_gconst, g_gconst);

    fp16 *ew16, *ep16, *eb_h, *wi_h, *pe_h, *ky_h, *en_h;
    fp16 *bhh_, *bch_, *qwh, *ehh, *ech, *h0h, *xch, *wch, *pch, *phh, *hh;
    cudaGetSymbolAddress((void**)&ew16, g_embW);
    cudaGetSymbolAddress((void**)&ep16, g_embP);
    cudaGetSymbolAddress((void**)&eb_h, g_emb_h);
    cudaGetSymbolAddress((void**)&wi_h, g_Wih_h);
    cudaGetSymbolAddress((void**)&pe_h, g_pWe_h);
    cudaGetSymbolAddress((void**)&ky_h, g_key_h);
    cudaGetSymbolAddress((void**)&en_h, g_enc_h);
    cudaGetSymbolAddress((void**)&bhh_, g_bhW_h);
    cudaGetSymbolAddress((void**)&bch_, g_bcW_h);
    cudaGetSymbolAddress((void**)&qwh, g_qW_h);
    cudaGetSymbolAddress((void**)&ehh, g_eh_h);
    cudaGetSymbolAddress((void**)&ech, g_ec_h);
    cudaGetSymbolAddress((void**)&h0h, g_h0h);
    cudaGetSymbolAddress((void**)&xch, g_xc_h);
    cudaGetSymbolAddress((void**)&wch, g_wc_h);
    cudaGetSymbolAddress((void**)&pch, g_pWc_h);
    cudaGetSymbolAddress((void**)&phh, g_pWh_h);
    cudaGetSymbolAddress((void**)&hh, g_hh);

    cudaFuncSetAttribute(mma_gemm<false, 0>, cudaFuncAttributeMaxDynamicSharedMemorySize, SMEM_DYN);
    cudaFuncSetAttribute(mma_gemm<false, 1>, cudaFuncAttributeMaxDynamicSharedMemorySize, SMEM_DYN);
    cudaFuncSetAttribute(mma_gemm<false, 2>, cudaFuncAttributeMaxDynamicSharedMemorySize, SMEM_DYN);
    cudaFuncSetAttribute(mma_gemm<false, 3>, cudaFuncAttributeMaxDynamicSharedMemorySize, SMEM_DYN);
    cudaFuncSetAttribute(mma_gemm<false, 4>, cudaFuncAttributeMaxDynamicSharedMemorySize, SMEM_DYN);
    cudaFuncSetAttribute(mma_gemm<true, 5>,  cudaFuncAttributeMaxDynamicSharedMemorySize, SMEM_DYN);

    // ---- fork ----
    cudaEventRecord(g_eFork, 0);
    cudaStreamWaitEvent(g_s1, g_eFork, 0);
    cudaStreamWaitEvent(g_s2, g_eFork, 0);

    // ===== s1: vocab precomputes (fp16 1-pass) =====
    cvt1_flat<<<cvt_grid(Vn * En / 4), 256, 0, g_s1>>>(emb, eb_h, Vn * En / 4);
    cvt1_kernel<<<H4, 64, 0, g_s1>>>(W_ih, En + H2, wi_h, En);
    cvt1_kernel<<<Hn, 64, 0, g_s1>>>(pre_W, En + Hn + H2, pe_h, En);
    mma_gemm<true, 5><<<dim3(H4 / 128, (Vn + 127) / 128), 128, SMEM_DYN, g_s1>>>(
        eb_h, eb_h, En, wi_h, wi_h, En, nullptr, H4, Vn, En, 4,
        nullptr, nullptr, nullptr, nullptr, ew16);
    cudaEventRecord(g_eEmbW, g_s1);
    mma_gemm<true, 5><<<dim3(Hn / 128, (Vn + 127) / 128), 128, SMEM_DYN, g_s1>>>(
        eb_h, eb_h, En, pe_h, pe_h, En, nullptr, Hn, Vn, En, 4,
        nullptr, nullptr, nullptr, nullptr, ep16);
    cudaEventRecord(g_eEmbP, g_s1);

    // ===== s2: qproj chain first (fp16 1-pass), then remaining weights =====
    cvt1_flat<<<cvt_grid(Hn * H2 / 4), 256, 0, g_s2>>>(bhW, bhh_, Hn * H2 / 4);
    cvt1_flat<<<cvt_grid(Bn * H2 / 4), 256, 0, g_s2>>>(eh, ehh, Bn * H2 / 4);
    cvt1_flat<<<cvt_grid(Hn * Hn / 4), 256, 0, g_s2>>>(query_W, qwh, Hn * Hn / 4);
    mma_gemm<false, 2><<<dim3(Hn / 128, 1), 128, SMEM_DYN, g_s2>>>(
        ehh, ehh, H2, bhh_, bhh_, H2, p_h0, Hn, Bn, H2, 16, bhb,
        nullptr, nullptr, nullptr, nullptr);
    cvt1_flat<<<cvt_grid(Bn * Hn / 4), 256, 0, g_s2>>>(p_h0, h0h, Bn * Hn / 4);
    mma_gemm<false, 0><<<dim3(Hn / 128, 1), 128, SMEM_DYN, g_s2>>>(
        h0h, h0h, Hn, qwh, qwh, Hn, p_qproj, Hn, Bn, Hn, 8,
        nullptr, nullptr, nullptr, nullptr, nullptr);
    cudaEventRecord(g_eQ, g_s2);
    xcat_h0<<<Bn, 256, 0, g_s2>>>();
    cvt1_flat<<<cvt_grid(Hn * H2 / 4), 256, 0, g_s2>>>(bcW, bch_, Hn * H2 / 4);
    cvt1_flat<<<cvt_grid(Bn * H2 / 4), 256, 0, g_s2>>>(ec, ech, Bn * H2 / 4);
    mma_gemm<false, 2><<<dim3(Hn / 128, 1), 128, SMEM_DYN, g_s2>>>(
        ech, ech, H2, bch_, bch_, H2, p_c0, Hn, Bn, H2, 16, bcb,
        nullptr, nullptr, nullptr, nullptr);
    pack_wcat1<<<H4, 256, 0, g_s2>>>(W_ih, W_hh);
    cvt1_kernel<<<Hn, 128, 0, g_s2>>>(pre_W + En, En + Hn + H2, phh, Hn);
    cvt1_kernel<<<Hn, 128, 0, g_s2>>>(pre_W + En + Hn, En + Hn + H2, pch, H2);
    cudaEventRecord(g_eS2, g_s2);

    // ===== s0: key + enc cvt, monolithic PK (1-pass fp16), attention =====
    cvt1_flat<<<cvt_grid(Hn * H2 / 4), 256>>>(key_W, ky_h, Hn * H2 / 4);
    cvt1_flat<<<1184, 256>>>(enc, en_h, Bn * Sn * H2 / 4);
    cudaStreamWaitEvent(0, g_eQ, 0);
    mma_gemm<false, 3><<<dim3(Hn / 128, (Bn * Sn) / 128), 128, SMEM_DYN>>>(
        en_h, en_h, H2, ky_h, ky_h, H2, p_part, 0, Bn * Sn, H2, 16, eW,
        nullptr, p_qproj, nullptr, nullptr);
    softmaxP<<<Bn, Sn>>>(srcpos);
    cudaStreamWaitEvent(0, g_eS2, 0);
    context_kernel<<<dim3(Bn, H2 / 256), 256>>>();
    cudaEventRecord(g_eCtx, 0);

    // ===== s2 continuation: ctxP concurrent with gconst =====
    cudaStreamWaitEvent(g_s2, g_eCtx, 0);
    mma_gemm<false, 0><<<dim3(Hn / 128, 1), 128, SMEM_DYN, g_s2>>>(
        xch, xch, 1536, pch, pch, H2, p_ctxP, Hn, Bn, H2, 16,
        nullptr, nullptr, nullptr, nullptr, nullptr);
    cudaEventRecord(g_eCtxP, g_s2);

    // ===== s0 continuation =====
    mma_gemm<false, 4><<<dim3(H4 / 128, 1, GK), 128, SMEM_DYN>>>(
        xch, xch, 1536, wch, wch, 1536, p_gpart, H4, Bn, 1536, 24 / GK,
        nullptr, nullptr, nullptr, nullptr, nullptr);
    reduceGK<<<(Bn * H4) / 256, 256>>>();
    cudaStreamWaitEvent(0, g_eEmbW, 0);
    gates_kernel<<<Bn * Tn, 256>>>(tgt, b_ih, b_hh);
    cudaStreamWaitEvent(0, g_eEmbP, 0);
    cudaStreamWaitEvent(0, g_eCtxP, 0);
    mma_gemm<false, 1><<<dim3(Hn / 128, (Bn * Tn) / 128), 128, SMEM_DYN>>>(
        hh, hh, Hn, phh, phh, Hn, out, Hn, Bn * Tn, Hn, 8,
        nullptr, tgt, (const float*)ep16, p_ctxP, nullptr);

    (void)in_sizes; (void)n_in; (void)out_size;
}